// round 9
// baseline (speedup 1.0000x reference)
#include <cuda_runtime.h>
#include <cstdint>

// Attention: B=4, H=16, D=64, N=2048, layout (b,h,d,n), fp32.
// Flash-attention with warp-level TF32 mma.sync (m16n8k8), fp32 accumulate.
// CTA = 128 queries (8 warps x m16 rows), streams K/V in 64-key tiles.

#define DHEAD 64
#define SEQ   2048
#define BM    128
#define BN    64
#define SSTR  68      // smem row stride in 4B words (conflict-free for fragment access)
#define NWARP 8
#define SMEM_WORDS (DHEAD*SSTR*2 + NWARP*16*SSTR)   // Ks + Vs + Ps
#define SMEM_BYTES (SMEM_WORDS*4)

__device__ __forceinline__ uint32_t f2tf(float x) {
    uint32_t r;
    asm("cvt.rna.tf32.f32 %0, %1;" : "=r"(r) : "f"(x));
    return r;
}

__device__ __forceinline__ float ex2(float x) {
    float y;
    asm("ex2.approx.ftz.f32 %0, %1;" : "=f"(y) : "f"(x));
    return y;
}

__device__ __forceinline__ void mma_tf32(float c[4], const uint32_t a[4],
                                         uint32_t b0, uint32_t b1) {
    asm volatile(
        "mma.sync.aligned.m16n8k8.row.col.f32.tf32.tf32.f32 "
        "{%0,%1,%2,%3}, {%4,%5,%6,%7}, {%8,%9}, {%0,%1,%2,%3};"
        : "+f"(c[0]), "+f"(c[1]), "+f"(c[2]), "+f"(c[3])
        : "r"(a[0]), "r"(a[1]), "r"(a[2]), "r"(a[3]), "r"(b0), "r"(b1));
}

extern __shared__ uint32_t smem[];

__global__ __launch_bounds__(256)
void attn_tf32_kernel(const float* __restrict__ qg,
                      const float* __restrict__ kg,
                      const float* __restrict__ vg,
                      float* __restrict__ og) {
    uint32_t* Ks = smem;                         // [DHEAD][SSTR]  tf32 bits, K[d][j]
    uint32_t* Vs = Ks + DHEAD * SSTR;            // [DHEAD][SSTR]  tf32 bits, V[d][j]
    uint32_t* Ps = Vs + DHEAD * SSTR;            // [NWARP][16][SSTR] tf32 P

    const int bh = blockIdx.y;
    const size_t hoff = (size_t)bh * DHEAD * SEQ;
    const float* qh = qg + hoff;
    const float* kh = kg + hoff;
    const float* vh = vg + hoff;
    float*       oh = og + hoff;

    const int tid  = threadIdx.x;
    const int w    = tid >> 5;
    const int lane = tid & 31;
    const int g    = lane >> 2;   // group id (row within m16 half)
    const int tg   = lane & 3;    // thread-in-group

    const int i0 = blockIdx.x * BM + w * 16;   // this warp's query base

    // ---- Load Q fragments once (A operand, m16 x k64), scale folded in ----
    // scores in log2 domain: S = (q * D^-0.5 * log2(e))^T K
    const float QS = 0.125f * 1.4426950408889634f;
    uint32_t afrag[8][4];
#pragma unroll
    for (int kk = 0; kk < 8; kk++) {
        const int d0 = kk * 8;
        afrag[kk][0] = f2tf(qh[(size_t)(d0 + tg)     * SEQ + i0 + g    ] * QS);
        afrag[kk][1] = f2tf(qh[(size_t)(d0 + tg)     * SEQ + i0 + g + 8] * QS);
        afrag[kk][2] = f2tf(qh[(size_t)(d0 + tg + 4) * SEQ + i0 + g    ] * QS);
        afrag[kk][3] = f2tf(qh[(size_t)(d0 + tg + 4) * SEQ + i0 + g + 8] * QS);
    }

    float oacc[8][4];
#pragma unroll
    for (int nt = 0; nt < 8; nt++) {
        oacc[nt][0] = 0.f; oacc[nt][1] = 0.f; oacc[nt][2] = 0.f; oacc[nt][3] = 0.f;
    }
    float m0 = -1e30f, m1 = -1e30f;   // running row maxima (log2 domain)
    float l0 = 0.f,    l1 = 0.f;      // running row sums

    uint32_t* Pw = Ps + w * 16 * SSTR;

    for (int jt = 0; jt < SEQ / BN; jt++) {
        const int j0 = jt * BN;
        __syncthreads();   // all warps done reading previous K/V tile

        // ---- Load K,V tile (64 x 64 each) as tf32 bits, vectorized ----
#pragma unroll
        for (int t = 0; t < 4; t++) {
            const int idx = tid + t * 256;       // 0..1023 float4 slots
            const int d   = idx >> 4;
            const int j4  = (idx & 15) * 4;
            float4 kv = *reinterpret_cast<const float4*>(kh + (size_t)d * SEQ + j0 + j4);
            uint4 kb;
            kb.x = f2tf(kv.x); kb.y = f2tf(kv.y); kb.z = f2tf(kv.z); kb.w = f2tf(kv.w);
            *reinterpret_cast<uint4*>(Ks + d * SSTR + j4) = kb;
            float4 vv = *reinterpret_cast<const float4*>(vh + (size_t)d * SEQ + j0 + j4);
            uint4 vb;
            vb.x = f2tf(vv.x); vb.y = f2tf(vv.y); vb.z = f2tf(vv.z); vb.w = f2tf(vv.w);
            *reinterpret_cast<uint4*>(Vs + d * SSTR + j4) = vb;
        }
        __syncthreads();

        // ---- S = Q^T K  (m16 x n64, k=64) ----
        float sacc[8][4];
#pragma unroll
        for (int nt = 0; nt < 8; nt++) {
            sacc[nt][0] = 0.f; sacc[nt][1] = 0.f; sacc[nt][2] = 0.f; sacc[nt][3] = 0.f;
        }
#pragma unroll
        for (int kk = 0; kk < 8; kk++) {
#pragma unroll
            for (int nt = 0; nt < 8; nt++) {
                uint32_t b0 = Ks[(kk * 8 + tg)     * SSTR + nt * 8 + g];
                uint32_t b1 = Ks[(kk * 8 + tg + 4) * SSTR + nt * 8 + g];
                mma_tf32(sacc[nt], afrag[kk], b0, b1);
            }
        }

        // ---- Online softmax (rows g and g+8) ----
        float tm0 = -1e30f, tm1 = -1e30f;
#pragma unroll
        for (int nt = 0; nt < 8; nt++) {
            tm0 = fmaxf(tm0, fmaxf(sacc[nt][0], sacc[nt][1]));
            tm1 = fmaxf(tm1, fmaxf(sacc[nt][2], sacc[nt][3]));
        }
        tm0 = fmaxf(tm0, __shfl_xor_sync(0xffffffffu, tm0, 1));
        tm0 = fmaxf(tm0, __shfl_xor_sync(0xffffffffu, tm0, 2));
        tm1 = fmaxf(tm1, __shfl_xor_sync(0xffffffffu, tm1, 1));
        tm1 = fmaxf(tm1, __shfl_xor_sync(0xffffffffu, tm1, 2));

        const float nm0 = fmaxf(m0, tm0);
        const float nm1 = fmaxf(m1, tm1);
        const float a0 = ex2(m0 - nm0);
        const float a1 = ex2(m1 - nm1);

        float rs0 = 0.f, rs1 = 0.f;
#pragma unroll
        for (int nt = 0; nt < 8; nt++) {
            float p00 = ex2(sacc[nt][0] - nm0);
            float p01 = ex2(sacc[nt][1] - nm0);
            float p10 = ex2(sacc[nt][2] - nm1);
            float p11 = ex2(sacc[nt][3] - nm1);
            rs0 += p00 + p01;
            rs1 += p10 + p11;
            uint32_t* pr0 = Pw + g * SSTR + nt * 8 + 2 * tg;
            pr0[0] = f2tf(p00); pr0[1] = f2tf(p01);
            uint32_t* pr1 = Pw + (g + 8) * SSTR + nt * 8 + 2 * tg;
            pr1[0] = f2tf(p10); pr1[1] = f2tf(p11);
        }
        rs0 += __shfl_xor_sync(0xffffffffu, rs0, 1);
        rs0 += __shfl_xor_sync(0xffffffffu, rs0, 2);
        rs1 += __shfl_xor_sync(0xffffffffu, rs1, 1);
        rs1 += __shfl_xor_sync(0xffffffffu, rs1, 2);

        l0 = l0 * a0 + rs0;
        l1 = l1 * a1 + rs1;
        m0 = nm0;
        m1 = nm1;

#pragma unroll
        for (int nt = 0; nt < 8; nt++) {
            oacc[nt][0] *= a0; oacc[nt][1] *= a0;
            oacc[nt][2] *= a1; oacc[nt][3] *= a1;
        }

        __syncwarp();   // P tile visible to whole warp

        // ---- O += P V^T  (A = P m16 x k64, B[k=j][n=d] = V[d][j]) ----
#pragma unroll
        for (int kk = 0; kk < 8; kk++) {
            uint32_t pa[4];
            pa[0] = Pw[(g)     * SSTR + kk * 8 + tg];
            pa[1] = Pw[(g + 8) * SSTR + kk * 8 + tg];
            pa[2] = Pw[(g)     * SSTR + kk * 8 + tg + 4];
            pa[3] = Pw[(g + 8) * SSTR + kk * 8 + tg + 4];
#pragma unroll
            for (int nt = 0; nt < 8; nt++) {
                uint32_t b0 = Vs[(nt * 8 + g) * SSTR + kk * 8 + tg];
                uint32_t b1 = Vs[(nt * 8 + g) * SSTR + kk * 8 + tg + 4];
                mma_tf32(oacc[nt], pa, b0, b1);
            }
        }
    }

    // ---- Epilogue: normalize and store out[d][i] ----
    const float il0 = 1.f / l0;
    const float il1 = 1.f / l1;
#pragma unroll
    for (int nt = 0; nt < 8; nt++) {
        const int d = nt * 8 + 2 * tg;
        oh[(size_t)(d)     * SEQ + i0 + g]     = oacc[nt][0] * il0;
        oh[(size_t)(d + 1) * SEQ + i0 + g]     = oacc[nt][1] * il0;
        oh[(size_t)(d)     * SEQ + i0 + g + 8] = oacc[nt][2] * il1;
        oh[(size_t)(d + 1) * SEQ + i0 + g + 8] = oacc[nt][3] * il1;
    }
}

extern "C" void kernel_launch(void* const* d_in, const int* in_sizes, int n_in,
                              void* d_out, int out_size) {
    const float* q = (const float*)d_in[0];
    const float* k = (const float*)d_in[1];
    const float* v = (const float*)d_in[2];
    float* o = (float*)d_out;

    const int bh = in_sizes[0] / (DHEAD * SEQ);   // B*H = 64

    // Opt-in to >48KB dynamic smem (idempotent; safe under graph capture).
    cudaFuncSetAttribute(attn_tf32_kernel,
                         cudaFuncAttributeMaxDynamicSharedMemorySize, SMEM_BYTES);

    dim3 grid(SEQ / BM, bh);
    attn_tf32_kernel<<<grid, 256, SMEM_BYTES>>>(q, k, v, o);
}

// round 11
// speedup vs baseline: 1.2367x; 1.2367x over previous
#include <cuda_runtime.h>
#include <cstdint>

// Attention B=4,H=16,D=64,N=2048, layout (b,h,d,n), fp32.
// TF32 mma.sync flash attention, LDS-optimized:
//  - CTA = 256 queries (8 warps x m32) -> halves per-row K/V smem traffic
//  - K/V stored as (pair, slot) layout: one conflict-free LDS.64 per B-fragment
//  - FA2 k-dim permutation: S accumulator C-frags reused DIRECTLY as P A-frags
//    (V stored with permuted j-pairs) -> no P smem round-trip, no shuffles.

#define SEQ 2048
#define DH  64
#define BM  256
#define BN  64
#define NTILES (SEQ / BN)

#define SSTR 136                 // words per (kk,tg) slot row (pads 128 -> conflict-free)
#define KP_WORDS (32 * SSTR)     // 4352 words = 17408 B
#define SMEM_WORDS (2 * KP_WORDS)

__device__ __forceinline__ uint32_t f2tf(float x) {
    uint32_t r;
    asm("cvt.rna.tf32.f32 %0, %1;" : "=r"(r) : "f"(x));
    return r;
}
__device__ __forceinline__ float ex2(float x) {
    float y;
    asm("ex2.approx.ftz.f32 %0, %1;" : "=f"(y) : "f"(x));
    return y;
}
__device__ __forceinline__ void mma_tf32(float c[4], const uint32_t a[4],
                                         uint32_t b0, uint32_t b1) {
    asm volatile(
        "mma.sync.aligned.m16n8k8.row.col.f32.tf32.tf32.f32 "
        "{%0,%1,%2,%3}, {%4,%5,%6,%7}, {%8,%9}, {%0,%1,%2,%3};"
        : "+f"(c[0]), "+f"(c[1]), "+f"(c[2]), "+f"(c[3])
        : "r"(a[0]), "r"(a[1]), "r"(a[2]), "r"(a[3]), "r"(b0), "r"(b1));
}

__global__ __launch_bounds__(256, 1)
void attn_tf32_kernel(const float* __restrict__ qg,
                      const float* __restrict__ kg,
                      const float* __restrict__ vg,
                      float* __restrict__ og) {
    __shared__ uint32_t smem[SMEM_WORDS];
    uint32_t* Kp = smem;               // [slot=kk*4+tg][pairs over j], pair = (d=kk*8+2tg, +1)
    uint32_t* Vp = smem + KP_WORDS;    // [slot=kk*4+tg][pairs over d], pair = (j=kk*8+2tg, +1)

    const int tid  = threadIdx.x;
    const int w    = tid >> 5;
    const int lane = tid & 31;
    const int g    = lane >> 2;        // 0..7
    const int tg   = lane & 3;         // 0..3

    const size_t hoff = (size_t)blockIdx.y * DH * SEQ;
    const float* qh = qg + hoff;
    const float* kh = kg + hoff;
    const float* vh = vg + hoff;
    float*       oh = og + hoff;
    const int i0 = blockIdx.x * BM;
    const int r0 = i0 + w * 32 + g;    // m-tile 0 row (m-tile 1 at +16)

    // ---- Q A-fragments (permuted d: k-slot s -> d = kk*8 + 2*(s&3) + (s>>2)) ----
    const float QS = 0.125f * 1.4426950408889634f;   // D^-0.5 * log2(e)
    uint32_t af[2][8][4];
#pragma unroll
    for (int mt = 0; mt < 2; mt++) {
#pragma unroll
        for (int kk = 0; kk < 8; kk++) {
            const int d0 = kk * 8 + 2 * tg;
            const float* q0 = qh + (size_t)d0 * SEQ + r0 + mt * 16;
            af[mt][kk][0] = f2tf(q0[0]       * QS);   // (row g,   k-slot tg)
            af[mt][kk][1] = f2tf(q0[8]       * QS);   // (row g+8, k-slot tg)
            af[mt][kk][2] = f2tf(q0[SEQ]     * QS);   // (row g,   k-slot tg+4)
            af[mt][kk][3] = f2tf(q0[SEQ + 8] * QS);   // (row g+8, k-slot tg+4)
        }
    }

    float oacc[2][8][4];
#pragma unroll
    for (int mt = 0; mt < 2; mt++)
#pragma unroll
        for (int nd = 0; nd < 8; nd++) {
            oacc[mt][nd][0] = 0.f; oacc[mt][nd][1] = 0.f;
            oacc[mt][nd][2] = 0.f; oacc[mt][nd][3] = 0.f;
        }
    float mr[4] = {-1e30f, -1e30f, -1e30f, -1e30f};  // rs = mt*2 + (row-half)
    float lr[4] = {0.f, 0.f, 0.f, 0.f};

    // ---- loader persona: thread owns gmem row d = tid&63, j-quads tid>>6 + 4*it ----
    const int ld_d  = tid & 63;
    const int ld_j0 = (tid >> 6) * 4;                      // 0,4,8,12
    const int kslot = (ld_d >> 3) * 4 + ((ld_d & 7) >> 1); // pair slot for this d
    const int kbase = kslot * SSTR + (ld_d & 1);           // + word-in-pair
    const float* krow = kh + (size_t)ld_d * SEQ;
    const float* vrow = vh + (size_t)ld_d * SEQ;

    for (int t = 0; t < NTILES; t++) {
        const int j0 = t * BN;
        __syncthreads();   // previous tile's reads complete

        // ---- stage K,V tile into pair layouts (tf32 bits) ----
#pragma unroll
        for (int it = 0; it < 4; it++) {
            const int j4 = ld_j0 + it * 16;                // 0..60 step 4 (per thread set)
            float4 kv = *reinterpret_cast<const float4*>(krow + j0 + j4);
            Kp[kbase + 2 * (j4 + 0)] = f2tf(kv.x);
            Kp[kbase + 2 * (j4 + 1)] = f2tf(kv.y);
            Kp[kbase + 2 * (j4 + 2)] = f2tf(kv.z);
            Kp[kbase + 2 * (j4 + 3)] = f2tf(kv.w);
            float4 vv = *reinterpret_cast<const float4*>(vrow + j0 + j4);
            const int vslot = (j4 >> 3) * 4 + ((j4 & 7) >> 1);
            uint2 pA; pA.x = f2tf(vv.x); pA.y = f2tf(vv.y);
            uint2 pB; pB.x = f2tf(vv.z); pB.y = f2tf(vv.w);
            *reinterpret_cast<uint2*>(Vp + (size_t)vslot       * SSTR + 2 * ld_d) = pA;
            *reinterpret_cast<uint2*>(Vp + (size_t)(vslot + 1) * SSTR + 2 * ld_d) = pB;
        }
        __syncthreads();

        // ---- S = Q^T K  (m32 x n64, k=64): 128 mma, 64 LDS.64 ----
        float sacc[2][8][4];
#pragma unroll
        for (int mt = 0; mt < 2; mt++)
#pragma unroll
            for (int nt = 0; nt < 8; nt++) {
                sacc[mt][nt][0] = 0.f; sacc[mt][nt][1] = 0.f;
                sacc[mt][nt][2] = 0.f; sacc[mt][nt][3] = 0.f;
            }
#pragma unroll
        for (int kk = 0; kk < 8; kk++) {
            const uint32_t* kb = Kp + (kk * 4 + tg) * SSTR;
#pragma unroll
            for (int nt = 0; nt < 8; nt++) {
                uint2 b = *reinterpret_cast<const uint2*>(kb + 2 * (nt * 8 + g));
                mma_tf32(sacc[0][nt], af[0][kk], b.x, b.y);
                mma_tf32(sacc[1][nt], af[1][kk], b.x, b.y);
            }
        }

        // ---- online softmax: 4 row-sets (mt x row-half); P -> tf32 in place ----
        float al[4];
#pragma unroll
        for (int mt = 0; mt < 2; mt++) {
#pragma unroll
            for (int hi = 0; hi < 2; hi++) {
                const int rs = mt * 2 + hi;
                float mx = -1e30f;
#pragma unroll
                for (int nt = 0; nt < 8; nt++)
                    mx = fmaxf(mx, fmaxf(sacc[mt][nt][hi * 2], sacc[mt][nt][hi * 2 + 1]));
                mx = fmaxf(mx, __shfl_xor_sync(0xffffffffu, mx, 1));
                mx = fmaxf(mx, __shfl_xor_sync(0xffffffffu, mx, 2));
                const float nm = fmaxf(mr[rs], mx);
                const float a  = ex2(mr[rs] - nm);
                float sum = 0.f;
#pragma unroll
                for (int nt = 0; nt < 8; nt++) {
                    float p0 = ex2(sacc[mt][nt][hi * 2]     - nm);
                    float p1 = ex2(sacc[mt][nt][hi * 2 + 1] - nm);
                    sum += p0 + p1;
                    sacc[mt][nt][hi * 2]     = __uint_as_float(f2tf(p0));
                    sacc[mt][nt][hi * 2 + 1] = __uint_as_float(f2tf(p1));
                }
                sum += __shfl_xor_sync(0xffffffffu, sum, 1);
                sum += __shfl_xor_sync(0xffffffffu, sum, 2);
                lr[rs] = lr[rs] * a + sum;
                mr[rs] = nm;
                al[rs] = a;
            }
        }
#pragma unroll
        for (int mt = 0; mt < 2; mt++)
#pragma unroll
            for (int nd = 0; nd < 8; nd++) {
                oacc[mt][nd][0] *= al[mt * 2];     oacc[mt][nd][1] *= al[mt * 2];
                oacc[mt][nd][2] *= al[mt * 2 + 1]; oacc[mt][nd][3] *= al[mt * 2 + 1];
            }

        // ---- O += P V^T : C-frags reused as A-frags {c0,c2,c1,c3} (permuted V) ----
#pragma unroll
        for (int kk = 0; kk < 8; kk++) {
            uint32_t pa0[4], pa1[4];
            pa0[0] = __float_as_uint(sacc[0][kk][0]);
            pa0[1] = __float_as_uint(sacc[0][kk][2]);
            pa0[2] = __float_as_uint(sacc[0][kk][1]);
            pa0[3] = __float_as_uint(sacc[0][kk][3]);
            pa1[0] = __float_as_uint(sacc[1][kk][0]);
            pa1[1] = __float_as_uint(sacc[1][kk][2]);
            pa1[2] = __float_as_uint(sacc[1][kk][1]);
            pa1[3] = __float_as_uint(sacc[1][kk][3]);
            const uint32_t* vb = Vp + (kk * 4 + tg) * SSTR;
#pragma unroll
            for (int nd = 0; nd < 8; nd++) {
                uint2 b = *reinterpret_cast<const uint2*>(vb + 2 * (nd * 8 + g));
                mma_tf32(oacc[0][nd], pa0, b.x, b.y);
                mma_tf32(oacc[1][nd], pa1, b.x, b.y);
            }
        }
    }

    // ---- epilogue: out[d][i] = oacc / l ----
    float inv[4];
#pragma unroll
    for (int rs = 0; rs < 4; rs++) inv[rs] = 1.f / lr[rs];
#pragma unroll
    for (int mt = 0; mt < 2; mt++) {
        const int r = r0 + mt * 16;
#pragma unroll
        for (int nd = 0; nd < 8; nd++) {
            const int d = nd * 8 + 2 * tg;
            oh[(size_t)d       * SEQ + r]     = oacc[mt][nd][0] * inv[mt * 2];
            oh[(size_t)(d + 1) * SEQ + r]     = oacc[mt][nd][1] * inv[mt * 2];
            oh[(size_t)d       * SEQ + r + 8] = oacc[mt][nd][2] * inv[mt * 2 + 1];
            oh[(size_t)(d + 1) * SEQ + r + 8] = oacc[mt][nd][3] * inv[mt * 2 + 1];
        }
    }
}

extern "C" void kernel_launch(void* const* d_in, const int* in_sizes, int n_in,
                              void* d_out, int out_size) {
    const float* q = (const float*)d_in[0];
    const float* k = (const float*)d_in[1];
    const float* v = (const float*)d_in[2];
    float* o = (float*)d_out;

    const int bh = in_sizes[0] / (DH * SEQ);   // B*H = 64
    dim3 grid(SEQ / BM, bh);
    attn_tf32_kernel<<<grid, 256>>>(q, k, v, o);
}